// round 6
// baseline (speedup 1.0000x reference)
#include <cuda_runtime.h>

#define NQ   4096
#define TI   128     // i-tile = threads per block
#define TJ   128     // j-tile
#define NT   (NQ/TJ) // 32 j-tiles
#define TCAP 4       // per-(point, j-tile) neighbor cap
#define CCAP 8       // compact per-point neighbor cap

// Scratch (__device__ globals; no allocations). Everything is fully
// overwritten each run -> deterministic, no zeroing, no atomics.
__device__ float4         g_pt4[NQ];                  // {x, y, pE, pJ}
__device__ unsigned short g_rankP[2][NQ][NT];         // partial rank sums
__device__ unsigned char  g_cntP [2][NQ][NT];         // per-tile neighbor counts
__device__ unsigned short g_nbrP [2][NQ][NT][TCAP];   // per-tile neighbor ids
__device__ unsigned short g_slot [2][NQ];             // final output slot (rank)
__device__ unsigned char  g_cntC [2][NQ];             // compact count (255=overflow)
__device__ unsigned short g_nbrC [2][NQ][CCAP];       // compact neighbor lists

// ---------------------------------------------------------------------------
// Per-point prep: 3-class softmax + point scaling. Deterministic across blocks.
// ---------------------------------------------------------------------------
__device__ __forceinline__ float4 prep_point(const float* __restrict__ logits,
                                             const float* __restrict__ boxes,
                                             float w, float h, int i, float* tgt) {
    float l0 = logits[3 * i + 0];
    float l1 = logits[3 * i + 1];
    float l2 = logits[3 * i + 2];
    float m  = fmaxf(l0, fmaxf(l1, l2));
    float e0 = expf(l0 - m);
    float e1 = expf(l1 - m);
    float e2 = expf(l2 - m);
    float s  = e0 + e1 + e2;
    float p0 = e0 / s;           // end_pt
    float p1 = e1 / s;           // junction_pt
    float p2 = e2 / s;           // background
    *tgt = 1.0f - p2;
    float x = boxes[2 * i + 0] * w;
    float y = boxes[2 * i + 1] * h;
    return make_float4(x, y, p0, p1);
}

// ---------------------------------------------------------------------------
// kA: fused prep + all-pairs. Block (bx,by): i in bx-tile vs j in by-tile.
// earlier(j,i) = bits(s_j) > bits(s_i) || (== && j < i)   (stable-sort order;
// softmax probs are nonneg finite -> IEEE bits are unsigned-order-monotone).
// ---------------------------------------------------------------------------
__global__ void kA_pairs(const float* __restrict__ logits,
                         const float* __restrict__ boxes,
                         const float* __restrict__ tsz,
                         float* __restrict__ out) {
    __shared__ float4 tile[TJ];   // {x, y, pE, pJ}

    int bx = blockIdx.x, by = blockIdx.y;
    int i  = bx * TI + threadIdx.x;
    int j0 = by * TJ;
    float w = tsz[0], h = tsz[1];

    float tgt_j;
    tile[threadIdx.x] = prep_point(logits, boxes, w, h, j0 + threadIdx.x, &tgt_j);
    float tgt_i;
    float4 me = prep_point(logits, boxes, w, h, i, &tgt_i);
    __syncthreads();

    if (by == 0) {
        out[5 * i + 0] = tgt_i;
        out[5 * i + 1] = me.x;
        out[5 * i + 2] = me.y;
        g_pt4[i] = me;
    }

    unsigned kE = __float_as_uint(me.z);
    unsigned kJ = __float_as_uint(me.w);
    int ilim = i - j0;            // lt = (jj < ilim)  <=>  j < i
    int rE = 0, rJ = 0, cE = 0, cJ = 0;
    unsigned short nbE[TCAP], nbJ[TCAP];

#pragma unroll 16
    for (int jj = 0; jj < TJ; jj++) {
        float4 q = tile[jj];                 // single broadcast LDS.128
        float dx = me.x - q.x;
        float dy = me.y - q.y;
        // match non-contracted dx*dx + dy*dy evaluation
        float d2 = __fadd_rn(__fmul_rn(dx, dx), __fmul_rn(dy, dy));
        unsigned qE = __float_as_uint(q.z);
        unsigned qJ = __float_as_uint(q.w);
        bool lt = jj < ilim;
        bool eE = (qE > kE) || ((qE == kE) && lt);
        bool eJ = (qJ > kJ) || ((qJ == kJ) && lt);
        rE += eE;
        rJ += eJ;
        if (d2 < 25.0f) {                    // rare (~0.03% of pairs)
            unsigned short j = (unsigned short)(j0 + jj);
            if (eE) { if (cE < TCAP) nbE[cE] = j; cE++; }
            if (eJ) { if (cJ < TCAP) nbJ[cJ] = j; cJ++; }
        }
    }

    g_rankP[0][i][by] = (unsigned short)rE;
    g_rankP[1][i][by] = (unsigned short)rJ;
    g_cntP[0][i][by]  = (unsigned char)min(cE, 255);
    g_cntP[1][i][by]  = (unsigned char)min(cJ, 255);
    int mE = min(cE, TCAP), mJ = min(cJ, TCAP);
    for (int k = 0; k < mE; k++) g_nbrP[0][i][by][k] = nbE[k];
    for (int k = 0; k < mJ; k++) g_nbrP[1][i][by][k] = nbJ[k];
}

// ---------------------------------------------------------------------------
// kG: per-point compaction (full-chip parallel, one thread per point).
//   slot(u) = sum of NT partial ranks; compact neighbor list <= CCAP (255=ovf)
// ---------------------------------------------------------------------------
__global__ void kG_gather() {
    int u = blockIdx.x * blockDim.x + threadIdx.x;
    if (u >= NQ) return;
#pragma unroll
    for (int ch = 0; ch < 2; ch++) {
        // rank sum: NT u16 = 64 bytes = 4 uint4
        const uint4* rp = (const uint4*)&g_rankP[ch][u][0];
        unsigned s = 0;
#pragma unroll
        for (int q = 0; q < NT / 8; q++) {
            uint4 a = rp[q];
            s += (a.x & 0xffffu) + (a.x >> 16) + (a.y & 0xffffu) + (a.y >> 16);
            s += (a.z & 0xffffu) + (a.z >> 16) + (a.w & 0xffffu) + (a.w >> 16);
        }
        g_slot[ch][u] = (unsigned short)s;

        // neighbor compaction: NT count bytes = 2 uint4
        const uint4* cp = (const uint4*)&g_cntP[ch][u][0];
        uint4 c0 = cp[0], c1 = cp[1];
        if ((c0.x | c0.y | c0.z | c0.w | c1.x | c1.y | c1.z | c1.w) == 0u) {
            g_cntC[ch][u] = 0;
            continue;
        }
        unsigned char cb[NT];
        *(uint4*)&cb[0]  = c0;
        *(uint4*)&cb[16] = c1;
        int pos = 0; bool ovf = false;
        for (int t = 0; t < NT; t++) {
            int c = cb[t];
            if (c == 0) continue;
            if (c > TCAP) { ovf = true; break; }
            for (int k = 0; k < c; k++) {
                if (pos < CCAP) g_nbrC[ch][u][pos] = g_nbrP[ch][u][t][k];
                pos++;
            }
        }
        g_cntC[ch][u] = (ovf || pos > CCAP) ? 255 : (unsigned char)pos;
    }
}

// ---------------------------------------------------------------------------
// kR: greedy-NMS fixpoint + scatter. Single block; per-thread unit state
// (cnt, valid, score, first neighbor) register-resident; keep[] in smem.
// earlier() is a strict total order => dependency DAG => chaotic sweeps
// converge to the unique greedy fixpoint. One BAR.RED per sweep.
// ---------------------------------------------------------------------------
__global__ void kR_resolve(float* __restrict__ out) {
    __shared__ unsigned char keep[2][NQ];
    int tid = threadIdx.x;

    // per-thread units: u = tid + k*1024, k in [0,4), ch in {0,1}
    float          sc  [4][2];
    unsigned char  cnt [4][2];
    unsigned short nb0 [4][2];

#pragma unroll
    for (int k = 0; k < 4; k++) {
        int u = tid + k * 1024;
        float4 p = g_pt4[u];
        sc[k][0] = p.z;  sc[k][1] = p.w;
        unsigned char vE = (p.z >= 0.05f) ? 1 : 0;
        unsigned char vJ = (p.w >= 0.05f) ? 1 : 0;
        keep[0][u] = vE;
        keep[1][u] = vJ;
        unsigned char c0 = g_cntC[0][u];
        unsigned char c1 = g_cntC[1][u];
        if (!vE) c0 = 0;            // kept==0 forever; nothing to sweep
        if (!vJ) c1 = 0;
        cnt[k][0] = c0;
        cnt[k][1] = c1;
        nb0[k][0] = (c0 >= 1 && c0 != 255) ? g_nbrC[0][u][0] : 0;
        nb0[k][1] = (c1 >= 1 && c1 != 255) ? g_nbrC[1][u][0] : 0;
    }
    __syncthreads();

    // fixpoint sweeps
    bool any;
    do {
        any = false;
#pragma unroll
        for (int k = 0; k < 4; k++) {
#pragma unroll
            for (int ch = 0; ch < 2; ch++) {
                int c = cnt[k][ch];
                if (c == 0) continue;
                int u = tid + k * 1024;
                bool nk;
                if (c == 1) {
                    nk = !keep[ch][nb0[k][ch]];
                } else if (c != 255) {
                    nk = !keep[ch][nb0[k][ch]];
                    for (int kk = 1; kk < c && nk; kk++)
                        nk = !keep[ch][g_nbrC[ch][u][kk]];
                } else {
                    // overflow fallback: exact rescan (P ~ 1e-9; correctness only)
                    float4 me = g_pt4[u];
                    float si = sc[k][ch];
                    nk = true;
                    for (int j = 0; j < NQ && nk; j++) {
                        float4 q = g_pt4[j];
                        float sj = (ch == 0) ? q.z : q.w;
                        bool e = (sj > si) || ((sj == si) && (j < u));
                        if (e && keep[ch][j]) {
                            float dx = me.x - q.x, dy = me.y - q.y;
                            float d2 = __fadd_rn(__fmul_rn(dx, dx), __fmul_rn(dy, dy));
                            if (d2 < 25.0f) nk = false;
                        }
                    }
                }
                if (nk != (bool)keep[ch][u]) {
                    keep[ch][u] = nk ? 1 : 0;
                    any = true;
                }
            }
        }
    } while (__syncthreads_or(any));

    // scatter NMS outputs to sorted slots
#pragma unroll
    for (int k = 0; k < 4; k++) {
        int u = tid + k * 1024;
#pragma unroll
        for (int ch = 0; ch < 2; ch++) {
            unsigned s = g_slot[ch][u];
            out[s * 5 + 3 + ch] = keep[ch][u] ? sc[k][ch] : 0.0f;
        }
    }
}

// ---------------------------------------------------------------------------
extern "C" void kernel_launch(void* const* d_in, const int* in_sizes, int n_in,
                              void* d_out, int out_size) {
    const float* logits = (const float*)d_in[0];  // [1,4096,3]
    const float* boxes  = (const float*)d_in[1];  // [1,4096,2]
    // d_in[2] = pred_gids (unused)
    const float* tsz    = (const float*)d_in[3];  // [1,2]
    float* out          = (float*)d_out;          // [1,4096,5]

    dim3 gA(NQ / TI, NQ / TJ);
    kA_pairs<<<gA, TI>>>(logits, boxes, tsz, out);
    kG_gather<<<NQ / 128, 128>>>();
    kR_resolve<<<1, 1024>>>(out);
}

// round 8
// speedup vs baseline: 1.1026x; 1.1026x over previous
#include <cuda_runtime.h>

#define NQ    4096
#define TI    128      // i-tile = threads per block
#define TJ    128      // j-tile
#define NT    (NQ/TJ)  // 32 j-tiles
#define GRID  64       // 64x64 spatial cells of 8px (>= 5px radius)
#define CELLS (GRID*GRID)
#define CELLCAP 12     // points per cell cap (overflow -> exact fallback)
#define CCAP  12       // per-point neighbor cap (overflow -> exact fallback)

// Scratch (__device__ globals; fully overwritten each run; no atomics on them)
__device__ float4         g_pt4[NQ];           // {x, y, pE, pJ}
__device__ unsigned short g_rankP[2][NQ][NT];  // partial rank sums

// ---------------------------------------------------------------------------
// Per-point prep: 3-class softmax + point scaling. Deterministic everywhere.
// ---------------------------------------------------------------------------
__device__ __forceinline__ float4 prep_point(const float* __restrict__ logits,
                                             const float* __restrict__ boxes,
                                             float w, float h, int i, float* tgt) {
    float l0 = logits[3 * i + 0];
    float l1 = logits[3 * i + 1];
    float l2 = logits[3 * i + 2];
    float m  = fmaxf(l0, fmaxf(l1, l2));
    float e0 = expf(l0 - m);
    float e1 = expf(l1 - m);
    float e2 = expf(l2 - m);
    float s  = e0 + e1 + e2;
    float p0 = e0 / s;           // end_pt
    float p1 = e1 / s;           // junction_pt
    float p2 = e2 / s;           // background
    *tgt = 1.0f - p2;
    float x = boxes[2 * i + 0] * w;
    float y = boxes[2 * i + 1] * h;
    return make_float4(x, y, p0, p1);
}

// earlier(j,i) = (s_j > s_i) || (s_j == s_i && j < i). Softmax probs are
// nonneg finite -> IEEE bits are unsigned-order-monotone, so with
// key = (bits << 12) | (4095 - idx) this is a single u64 compare.
__device__ __forceinline__ unsigned long long mk_key(float p, int idx) {
    return (((unsigned long long)__float_as_uint(p)) << 12) |
           (unsigned long long)(NQ - 1 - idx);
}

// ---------------------------------------------------------------------------
// kA: fused prep + all-pairs RANK ONLY (no distances).
// rank(i) = #{ j : key_j > key_i } accumulated as per-tile partials.
// ---------------------------------------------------------------------------
__global__ void kA_rank(const float* __restrict__ logits,
                        const float* __restrict__ boxes,
                        const float* __restrict__ tsz,
                        float* __restrict__ out) {
    __shared__ ulonglong2 tile[TJ];   // {keyE, keyJ} per j

    int bx = blockIdx.x, by = blockIdx.y;
    int i  = bx * TI + threadIdx.x;
    int jg = by * TJ + threadIdx.x;
    float w = tsz[0], h = tsz[1];

    float tgt_j;
    float4 pj = prep_point(logits, boxes, w, h, jg, &tgt_j);
    tile[threadIdx.x] = make_ulonglong2(mk_key(pj.z, jg), mk_key(pj.w, jg));

    float4 me;
    float tgt_i;
    if (bx == by) {                     // i == jg (TI == TJ): reuse
        me = pj; tgt_i = tgt_j;
    } else {
        me = prep_point(logits, boxes, w, h, i, &tgt_i);
    }
    __syncthreads();

    if (by == 0) {
        out[5 * i + 0] = tgt_i;
        out[5 * i + 1] = me.x;
        out[5 * i + 2] = me.y;
        g_pt4[i] = me;
    }

    unsigned long long kE = mk_key(me.z, i);
    unsigned long long kJ = mk_key(me.w, i);
    int rE = 0, rJ = 0;

#pragma unroll 16
    for (int jj = 0; jj < TJ; jj++) {
        ulonglong2 q = tile[jj];        // one broadcast LDS.128 per pair
        rE += (q.x > kE);
        rJ += (q.y > kJ);
    }

    g_rankP[0][i][by] = (unsigned short)rE;
    g_rankP[1][i][by] = (unsigned short)rJ;
}

// ---------------------------------------------------------------------------
// kR: single block. Spatial-hash neighbor build (smem) + greedy-NMS fixpoint
// + rank-sum scatter. earlier() is a strict total order => dependency DAG =>
// chaotic sweeps converge to the unique greedy fixpoint (neighbor order and
// atomic binning order are irrelevant to the result).
// ---------------------------------------------------------------------------
extern __shared__ char dsm[];

__global__ void kR_resolve(float* __restrict__ out) {
    float4*        spts  = (float4*)dsm;                           // 65536 B
    unsigned int*  ccnt  = (unsigned int*)(dsm + 65536);           // 16384 B
    unsigned short* slots = (unsigned short*)(dsm + 81920);        // 98304 B
    unsigned char* keep  = (unsigned char*)(dsm + 180224);         // 8192 B

    int tid = threadIdx.x;

    // load points, init keep, zero cell counters
#pragma unroll
    for (int k = 0; k < 4; k++) {
        int u = tid + k * 1024;
        float4 p = g_pt4[u];
        spts[u] = p;
        keep[u]      = (p.z >= 0.05f) ? 1 : 0;
        keep[NQ + u] = (p.w >= 0.05f) ? 1 : 0;
        ccnt[u] = 0;
    }
    __syncthreads();

    // bin points into 64x64 cells (8px)
    int mycell[4];
#pragma unroll
    for (int k = 0; k < 4; k++) {
        int u = tid + k * 1024;
        float4 p = spts[u];
        int cx = min(GRID - 1, max(0, (int)(p.x * 0.125f)));
        int cy = min(GRID - 1, max(0, (int)(p.y * 0.125f)));
        int cell = cy * GRID + cx;
        mycell[k] = cell;
        unsigned s = atomicAdd(&ccnt[cell], 1u);
        if (s < CELLCAP) slots[cell * CELLCAP + s] = (unsigned short)u;
    }
    __syncthreads();

    // neighbor build: earlier-neighbors within dist<5 via 3x3 cell scan
    float          sc [4][2];
    unsigned char  cnt[4][2];        // 255 = overflow -> exact fallback
    unsigned short nb0[4][2];
    unsigned short nbL[4][2][CCAP];

#pragma unroll
    for (int k = 0; k < 4; k++) {
        int u = tid + k * 1024;
        float4 p = spts[u];
        sc[k][0] = p.z; sc[k][1] = p.w;
        int cx = mycell[k] % GRID, cy = mycell[k] / GRID;
        int cE = 0, cJ = 0;
        bool ovf = false;
        for (int dy = -1; dy <= 1; dy++) {
            int yy = cy + dy;
            if (yy < 0 || yy >= GRID) continue;
            for (int dx = -1; dx <= 1; dx++) {
                int xx = cx + dx;
                if (xx < 0 || xx >= GRID) continue;
                int cell = yy * GRID + xx;
                unsigned n = ccnt[cell];
                if (n > CELLCAP) { ovf = true; n = CELLCAP; }
                for (unsigned s = 0; s < n; s++) {
                    int v = slots[cell * CELLCAP + s];
                    float4 q = spts[v];
                    float ddx = p.x - q.x, ddy = p.y - q.y;
                    float d2 = __fadd_rn(__fmul_rn(ddx, ddx), __fmul_rn(ddy, ddy));
                    if (d2 < 25.0f) {
                        if ((q.z > p.z) || ((q.z == p.z) && (v < u))) {
                            if (cE < CCAP) nbL[k][0][cE] = (unsigned short)v;
                            cE++;
                        }
                        if ((q.w > p.w) || ((q.w == p.w) && (v < u))) {
                            if (cJ < CCAP) nbL[k][1][cJ] = (unsigned short)v;
                            cJ++;
                        }
                    }
                }
            }
        }
        unsigned char ce = (ovf || cE > CCAP) ? 255 : (unsigned char)cE;
        unsigned char cj = (ovf || cJ > CCAP) ? 255 : (unsigned char)cJ;
        if (!keep[u])      ce = 0;   // invalid: kept==0 forever, nothing to sweep
        if (!keep[NQ + u]) cj = 0;
        cnt[k][0] = ce; cnt[k][1] = cj;
        nb0[k][0] = (ce >= 1 && ce != 255) ? nbL[k][0][0] : 0;
        nb0[k][1] = (cj >= 1 && cj != 255) ? nbL[k][1][0] : 0;
    }
    __syncthreads();

    // fixpoint sweeps (one BAR.RED per sweep)
    bool any;
    do {
        any = false;
#pragma unroll
        for (int k = 0; k < 4; k++) {
#pragma unroll
            for (int ch = 0; ch < 2; ch++) {
                int c = cnt[k][ch];
                if (c == 0) continue;
                int u = tid + k * 1024;
                bool nk;
                if (c == 1) {
                    nk = !keep[ch * NQ + nb0[k][ch]];
                } else if (c != 255) {
                    nk = !keep[ch * NQ + nb0[k][ch]];
                    for (int kk = 1; kk < c && nk; kk++)
                        nk = !keep[ch * NQ + nbL[k][ch][kk]];
                } else {
                    // exact fallback (P ~ 1e-9): full rescan from smem
                    float4 mep = spts[u];
                    float si = sc[k][ch];
                    nk = true;
                    for (int j = 0; j < NQ && nk; j++) {
                        float4 q = spts[j];
                        float sj = (ch == 0) ? q.z : q.w;
                        bool e = (sj > si) || ((sj == si) && (j < u));
                        if (e && keep[ch * NQ + j]) {
                            float ddx = mep.x - q.x, ddy = mep.y - q.y;
                            float d2 = __fadd_rn(__fmul_rn(ddx, ddx), __fmul_rn(ddy, ddy));
                            if (d2 < 25.0f) nk = false;
                        }
                    }
                }
                if (nk != (bool)keep[ch * NQ + u]) {
                    keep[ch * NQ + u] = nk ? 1 : 0;
                    any = true;
                }
            }
        }
    } while (__syncthreads_or(any));

    // rank-sum + scatter to sorted slots (ranks form a permutation)
#pragma unroll
    for (int k = 0; k < 4; k++) {
        int u = tid + k * 1024;
#pragma unroll
        for (int ch = 0; ch < 2; ch++) {
            const uint4* rp = (const uint4*)&g_rankP[ch][u][0];
            unsigned s = 0;
#pragma unroll
            for (int q = 0; q < NT / 8; q++) {
                uint4 a = rp[q];
                s += (a.x & 0xffffu) + (a.x >> 16) + (a.y & 0xffffu) + (a.y >> 16);
                s += (a.z & 0xffffu) + (a.z >> 16) + (a.w & 0xffffu) + (a.w >> 16);
            }
            out[s * 5 + 3 + ch] = keep[ch * NQ + u] ? sc[k][ch] : 0.0f;
        }
    }
}

// ---------------------------------------------------------------------------
#define KR_SMEM (65536 + 16384 + 98304 + 8192)

extern "C" void kernel_launch(void* const* d_in, const int* in_sizes, int n_in,
                              void* d_out, int out_size) {
    const float* logits = (const float*)d_in[0];  // [1,4096,3]
    const float* boxes  = (const float*)d_in[1];  // [1,4096,2]
    // d_in[2] = pred_gids (unused)
    const float* tsz    = (const float*)d_in[3];  // [1,2]
    float* out          = (float*)d_out;          // [1,4096,5]

    // host-side attribute set: runs during capture only, not in the graph
    cudaFuncSetAttribute(kR_resolve,
                         cudaFuncAttributeMaxDynamicSharedMemorySize, KR_SMEM);

    dim3 gA(NQ / TI, NQ / TJ);
    kA_rank<<<gA, TI>>>(logits, boxes, tsz, out);
    kR_resolve<<<1, 1024, KR_SMEM>>>(out);
}

// round 10
// speedup vs baseline: 1.3301x; 1.2063x over previous
#include <cuda_runtime.h>

#define NQ    4096
#define TI    128       // i-tile = threads per block
#define TJ    128       // j-tile
#define NT    (NQ/TJ)   // 32 j-tiles
#define GRID  64        // 64x64 spatial cells of 8px (>= 5px radius)
#define CELLS (GRID*GRID)
#define CELLCAP 8       // points per cell cap (overflow -> exact fallback)
#define CCAP    8       // per-point neighbor cap (overflow -> exact fallback)

// Scratch (__device__ globals; fully overwritten each run)
__device__ float4             g_pt4[NQ];             // {x, y, pE, pJ}
__device__ unsigned short     g_rankP[2][NQ][NT];    // partial rank sums
__device__ unsigned int       g_ccnt[CELLS];         // cell counts (atomic)
__device__ unsigned short     g_cslot[CELLS*CELLCAP];// cell -> point ids
__device__ unsigned long long g_unit[2][NQ];         // {cnt:8|nb0:16|nb1:16|slot:16}
__device__ unsigned short     g_nbrC[2][NQ][CCAP];   // full neighbor lists

// ---------------------------------------------------------------------------
// Per-point prep: 3-class softmax + point scaling. Deterministic everywhere.
// ---------------------------------------------------------------------------
__device__ __forceinline__ float4 prep_point(const float* __restrict__ logits,
                                             const float* __restrict__ boxes,
                                             float w, float h, int i, float* tgt) {
    float l0 = logits[3 * i + 0];
    float l1 = logits[3 * i + 1];
    float l2 = logits[3 * i + 2];
    float m  = fmaxf(l0, fmaxf(l1, l2));
    float e0 = expf(l0 - m);
    float e1 = expf(l1 - m);
    float e2 = expf(l2 - m);
    float s  = e0 + e1 + e2;
    float p0 = e0 / s;           // end_pt
    float p1 = e1 / s;           // junction_pt
    float p2 = e2 / s;           // background
    *tgt = 1.0f - p2;
    float x = boxes[2 * i + 0] * w;
    float y = boxes[2 * i + 1] * h;
    return make_float4(x, y, p0, p1);
}

// earlier(j,i) = (s_j > s_i) || (s_j == s_i && j < i). Softmax probs are
// nonneg finite -> IEEE bits are unsigned-order-monotone, so with
// key = (bits << 12) | (4095 - idx) this is a single u64 compare.
__device__ __forceinline__ unsigned long long mk_key(float p, int idx) {
    return (((unsigned long long)__float_as_uint(p)) << 12) |
           (unsigned long long)(NQ - 1 - idx);
}

// ---------------------------------------------------------------------------
// kA: fused prep + all-pairs RANK ONLY. by==1 blocks also zero cell counters
// (consumed only by kB, which runs after kA completes).
// ---------------------------------------------------------------------------
__global__ void kA_rank(const float* __restrict__ logits,
                        const float* __restrict__ boxes,
                        const float* __restrict__ tsz,
                        float* __restrict__ out) {
    __shared__ ulonglong2 tile[TJ];   // {keyE, keyJ} per j

    int bx = blockIdx.x, by = blockIdx.y;
    int i  = bx * TI + threadIdx.x;
    int jg = by * TJ + threadIdx.x;
    float w = tsz[0], h = tsz[1];

    if (by == 1) g_ccnt[bx * TI + threadIdx.x] = 0;   // 32*128 == CELLS

    float tgt_j;
    float4 pj = prep_point(logits, boxes, w, h, jg, &tgt_j);
    tile[threadIdx.x] = make_ulonglong2(mk_key(pj.z, jg), mk_key(pj.w, jg));

    float4 me;
    float tgt_i;
    if (bx == by) {                     // i == jg (TI == TJ): reuse
        me = pj; tgt_i = tgt_j;
    } else {
        me = prep_point(logits, boxes, w, h, i, &tgt_i);
    }
    __syncthreads();

    if (by == 0) {
        out[5 * i + 0] = tgt_i;
        out[5 * i + 1] = me.x;
        out[5 * i + 2] = me.y;
        g_pt4[i] = me;
    }

    unsigned long long kE = mk_key(me.z, i);
    unsigned long long kJ = mk_key(me.w, i);
    int rE = 0, rJ = 0;

#pragma unroll 16
    for (int jj = 0; jj < TJ; jj++) {
        ulonglong2 q = tile[jj];        // one broadcast LDS.128 per pair
        rE += (q.x > kE);
        rJ += (q.y > kJ);
    }

    g_rankP[0][i][by] = (unsigned short)rE;
    g_rankP[1][i][by] = (unsigned short)rJ;
}

// ---------------------------------------------------------------------------
// kB: bin points into the global 64x64 cell grid (full-chip, atomics).
// ---------------------------------------------------------------------------
__global__ void kB_bin() {
    int u = blockIdx.x * blockDim.x + threadIdx.x;
    float4 p = g_pt4[u];
    int cx = min(GRID - 1, max(0, (int)(p.x * 0.125f)));
    int cy = min(GRID - 1, max(0, (int)(p.y * 0.125f)));
    int cell = cy * GRID + cx;
    unsigned s = atomicAdd(&g_ccnt[cell], 1u);
    if (s < CELLCAP) g_cslot[cell * CELLCAP + s] = (unsigned short)u;
}

// ---------------------------------------------------------------------------
// kC: per-point neighbor build (3x3 cells) + rank-sum -> packed unit state.
// unit = cnt | nb0<<8 | nb1<<24 | slot<<40.  cnt==255 -> exact fallback in kR.
// Invalid points (score < 0.05) get cnt=0 (kept==0 forever, nothing to sweep).
// ---------------------------------------------------------------------------
__global__ void kC_nbr() {
    int u = blockIdx.x * blockDim.x + threadIdx.x;
    float4 p = g_pt4[u];
    int cx = min(GRID - 1, max(0, (int)(p.x * 0.125f)));
    int cy = min(GRID - 1, max(0, (int)(p.y * 0.125f)));

    int cE = 0, cJ = 0;
    bool ovf = false;
    unsigned short nbE[CCAP], nbJ[CCAP];
    bool vE = (p.z >= 0.05f);
    bool vJ = (p.w >= 0.05f);

    if (vE || vJ) {
        for (int dy = -1; dy <= 1; dy++) {
            int yy = cy + dy;
            if (yy < 0 || yy >= GRID) continue;
            for (int dx = -1; dx <= 1; dx++) {
                int xx = cx + dx;
                if (xx < 0 || xx >= GRID) continue;
                int cell = yy * GRID + xx;
                unsigned n = g_ccnt[cell];
                if (n > CELLCAP) { ovf = true; n = CELLCAP; }
                for (unsigned s = 0; s < n; s++) {
                    int v = g_cslot[cell * CELLCAP + s];
                    float4 q = g_pt4[v];
                    float ddx = p.x - q.x, ddy = p.y - q.y;
                    float d2 = __fadd_rn(__fmul_rn(ddx, ddx), __fmul_rn(ddy, ddy));
                    if (d2 < 25.0f) {
                        if ((q.z > p.z) || ((q.z == p.z) && (v < u))) {
                            if (cE < CCAP) nbE[cE] = (unsigned short)v;
                            cE++;
                        }
                        if ((q.w > p.w) || ((q.w == p.w) && (v < u))) {
                            if (cJ < CCAP) nbJ[cJ] = (unsigned short)v;
                            cJ++;
                        }
                    }
                }
            }
        }
    }

    unsigned long long ce = (ovf || cE > CCAP) ? 255u : (unsigned)cE;
    unsigned long long cj = (ovf || cJ > CCAP) ? 255u : (unsigned)cJ;
    if (!vE) ce = 0;
    if (!vJ) cj = 0;

#pragma unroll
    for (int ch = 0; ch < 2; ch++) {
        const uint4* rp = (const uint4*)&g_rankP[ch][u][0];
        unsigned long long slot = 0;
#pragma unroll
        for (int q = 0; q < NT / 8; q++) {
            uint4 a = rp[q];
            slot += (a.x & 0xffffu) + (a.x >> 16) + (a.y & 0xffffu) + (a.y >> 16);
            slot += (a.z & 0xffffu) + (a.z >> 16) + (a.w & 0xffffu) + (a.w >> 16);
        }
        unsigned long long c  = (ch == 0) ? ce : cj;
        unsigned short*   nb  = (ch == 0) ? nbE : nbJ;
        int               cnt = (ch == 0) ? cE : cJ;
        unsigned long long n0 = 0, n1 = 0;
        if (c >= 1 && c != 255) n0 = nb[0];
        if (c >= 2 && c != 255) n1 = nb[1];
        g_unit[ch][u] = c | (n0 << 8) | (n1 << 24) | (slot << 40);
        int m = min(cnt, CCAP);
        if (c != 255)
            for (int k = 2; k < m; k++) g_nbrC[ch][u][k] = nb[k];
    }
}

// ---------------------------------------------------------------------------
// kR: greedy-NMS fixpoint + scatter only. Single block; per-unit state is one
// LDG.64 -> registers (static indices only, no local memory); keep[] in smem.
// earlier() is a strict total order => dependency DAG => chaotic sweeps
// converge to the unique greedy fixpoint. One BAR.RED per sweep.
// ---------------------------------------------------------------------------
__global__ void kR_resolve(float* __restrict__ out) {
    __shared__ unsigned char keep[2 * NQ];
    int tid = threadIdx.x;

    float          sc  [4][2];
    unsigned char  cnt [4][2];
    unsigned short nb0 [4][2];
    unsigned short nb1 [4][2];
    unsigned short slot[4][2];

#pragma unroll
    for (int k = 0; k < 4; k++) {
        int u = tid + k * 1024;
        float4 p = g_pt4[u];
        sc[k][0] = p.z;  sc[k][1] = p.w;
        keep[u]      = (p.z >= 0.05f) ? 1 : 0;
        keep[NQ + u] = (p.w >= 0.05f) ? 1 : 0;
#pragma unroll
        for (int ch = 0; ch < 2; ch++) {
            unsigned long long t = g_unit[ch][u];
            cnt [k][ch] = (unsigned char)(t & 0xff);
            nb0 [k][ch] = (unsigned short)((t >> 8)  & 0xffff);
            nb1 [k][ch] = (unsigned short)((t >> 24) & 0xffff);
            slot[k][ch] = (unsigned short)(t >> 40);
        }
    }
    __syncthreads();

    bool any;
    do {
        any = false;
#pragma unroll
        for (int k = 0; k < 4; k++) {
#pragma unroll
            for (int ch = 0; ch < 2; ch++) {
                int c = cnt[k][ch];
                if (c == 0) continue;
                int u = tid + k * 1024;
                bool nk;
                if (c == 1) {
                    nk = !keep[ch * NQ + nb0[k][ch]];
                } else if (c == 2) {
                    nk = !keep[ch * NQ + nb0[k][ch]] &&
                         !keep[ch * NQ + nb1[k][ch]];
                } else if (c != 255) {
                    nk = !keep[ch * NQ + nb0[k][ch]] &&
                         !keep[ch * NQ + nb1[k][ch]];
                    for (int kk = 2; kk < c && nk; kk++)
                        nk = !keep[ch * NQ + g_nbrC[ch][u][kk]];
                } else {
                    // exact fallback (P ~ 1e-9): full rescan from global
                    float4 mep = g_pt4[u];
                    float si = sc[k][ch];
                    nk = true;
                    for (int j = 0; j < NQ && nk; j++) {
                        float4 q = g_pt4[j];
                        float sj = (ch == 0) ? q.z : q.w;
                        bool e = (sj > si) || ((sj == si) && (j < u));
                        if (e && keep[ch * NQ + j]) {
                            float ddx = mep.x - q.x, ddy = mep.y - q.y;
                            float d2 = __fadd_rn(__fmul_rn(ddx, ddx), __fmul_rn(ddy, ddy));
                            if (d2 < 25.0f) nk = false;
                        }
                    }
                }
                if (nk != (bool)keep[ch * NQ + u]) {
                    keep[ch * NQ + u] = nk ? 1 : 0;
                    any = true;
                }
            }
        }
    } while (__syncthreads_or(any));

    // scatter NMS outputs to sorted slots (slots form a permutation)
#pragma unroll
    for (int k = 0; k < 4; k++) {
        int u = tid + k * 1024;
#pragma unroll
        for (int ch = 0; ch < 2; ch++) {
            out[slot[k][ch] * 5 + 3 + ch] =
                keep[ch * NQ + u] ? sc[k][ch] : 0.0f;
        }
    }
}

// ---------------------------------------------------------------------------
extern "C" void kernel_launch(void* const* d_in, const int* in_sizes, int n_in,
                              void* d_out, int out_size) {
    const float* logits = (const float*)d_in[0];  // [1,4096,3]
    const float* boxes  = (const float*)d_in[1];  // [1,4096,2]
    // d_in[2] = pred_gids (unused)
    const float* tsz    = (const float*)d_in[3];  // [1,2]
    float* out          = (float*)d_out;          // [1,4096,5]

    dim3 gA(NQ / TI, NQ / TJ);
    kA_rank<<<gA, TI>>>(logits, boxes, tsz, out);
    kB_bin<<<NQ / 128, 128>>>();
    kC_nbr<<<NQ / 128, 128>>>();
    kR_resolve<<<1, 1024>>>(out);
}